// round 2
// baseline (speedup 1.0000x reference)
#include <cuda_runtime.h>

// DilateAttention: B=8, C=384 (12 heads x 32), H=W=56, kernel 3x3, dilation 2, pad 2.
// q,k,v: [B, C, H, W] f32. out: [B, H, W, C] f32.
// Smem-tiled: block = (ytile, head, b). 448 threads = 8 rows x 56 cols of pixels.
// Channel-chunked (8 at a time): k-tile -> logits, softmax, v-tile -> output.
// Zero-padded smem halo reproduces unfold's zero padding exactly (OOB logit == 0).

#define HD     32
#define HEADS  12
#define WD     56
#define HT     56
#define BD     8
#define HW     (WD * HT)
#define CTOT   (HEADS * HD)

#define TY     8            // pixel rows per block
#define ROWS   12           // TY + 2*dilation halo
#define SW     60           // 56 + 2*dilation halo
#define CC     8            // channels per chunk
#define NCH    (HD / CC)    // 4 chunks
#define NTHR   (TY * WD)    // 448

__global__ __launch_bounds__(NTHR)
void dilate_attn_kernel(const float* __restrict__ q,
                        const float* __restrict__ k,
                        const float* __restrict__ v,
                        float* __restrict__ out)
{
    __shared__ float sTile[CC][ROWS][SW];   // 23040 B
    __shared__ float sStage[NTHR][CC + 1];  // 16128 B (pad avoids bank conflicts)

    const int y0   = blockIdx.x * TY;
    const int head = blockIdx.y;
    const int b    = blockIdx.z;

    const int tid  = threadIdx.x;
    const int ly   = tid / WD;          // 0..7
    const int x    = tid % WD;          // 0..55
    const int gy   = y0 + ly;
    const int pix  = gy * WD + x;

    const int base = (b * CTOT + head * HD) * HW;

    const float scale = 0.17677669529663687f;  // 32^-0.5

    float attn[9];
#pragma unroll
    for (int p = 0; p < 9; p++) attn[p] = 0.0f;

    // ================= K phase: accumulate logits =================
    for (int ch = 0; ch < NCH; ch++) {
        const int c0 = ch * CC;
        __syncthreads();  // protect previous chunk's tile
        // cooperative load of k tile (zero-padded halo)
        for (int i = tid; i < CC * ROWS * SW; i += NTHR) {
            int c   = i / (ROWS * SW);
            int rem = i % (ROWS * SW);
            int r   = rem / SW;
            int xl  = rem % SW;
            int gyy = y0 - 2 + r;
            int gxx = xl - 2;
            float val = 0.0f;
            if ((unsigned)gyy < (unsigned)HT && (unsigned)gxx < (unsigned)WD)
                val = k[base + (c0 + c) * HW + gyy * WD + gxx];
            sTile[c][r][xl] = val;
        }
        __syncthreads();

        float qv[CC];
#pragma unroll
        for (int c = 0; c < CC; c++) qv[c] = q[base + (c0 + c) * HW + pix];

#pragma unroll
        for (int py = 0; py < 3; py++) {
#pragma unroll
            for (int px = 0; px < 3; px++) {
                float acc = attn[py * 3 + px];
#pragma unroll
                for (int c = 0; c < CC; c++)
                    acc = fmaf(qv[c], sTile[c][ly + 2 * py][x + 2 * px], acc);
                attn[py * 3 + px] = acc;
            }
        }
    }

    // ================= softmax over 9 (inv folded into weights) =================
    {
        float m = attn[0] * scale;
#pragma unroll
        for (int p = 0; p < 9; p++) { attn[p] *= scale; m = fmaxf(m, attn[p]); }
        float denom = 0.0f;
#pragma unroll
        for (int p = 0; p < 9; p++) { attn[p] = __expf(attn[p] - m); denom += attn[p]; }
        float inv = 1.0f / denom;
#pragma unroll
        for (int p = 0; p < 9; p++) attn[p] *= inv;
    }

    // ================= V phase: weighted sum, staged coalesced store =================
    const int obase = ((b * HT + y0) * WD) * CTOT + head * HD;  // pixel (y0,0), chunk channel 0

    for (int ch = 0; ch < NCH; ch++) {
        const int c0 = ch * CC;
        __syncthreads();  // protect tile + previous stage
        for (int i = tid; i < CC * ROWS * SW; i += NTHR) {
            int c   = i / (ROWS * SW);
            int rem = i % (ROWS * SW);
            int r   = rem / SW;
            int xl  = rem % SW;
            int gyy = y0 - 2 + r;
            int gxx = xl - 2;
            float val = 0.0f;
            if ((unsigned)gyy < (unsigned)HT && (unsigned)gxx < (unsigned)WD)
                val = v[base + (c0 + c) * HW + gyy * WD + gxx];
            sTile[c][r][xl] = val;
        }
        __syncthreads();

        float acc[CC];
#pragma unroll
        for (int c = 0; c < CC; c++) acc[c] = 0.0f;
#pragma unroll
        for (int py = 0; py < 3; py++) {
#pragma unroll
            for (int px = 0; px < 3; px++) {
                float w = attn[py * 3 + px];
#pragma unroll
                for (int c = 0; c < CC; c++)
                    acc[c] = fmaf(w, sTile[c][ly + 2 * py][x + 2 * px], acc[c]);
            }
        }

#pragma unroll
        for (int c = 0; c < CC; c++) sStage[tid][c] = acc[c];
        __syncthreads();

        // cooperative store: 8 consecutive lanes write one pixel's 8-channel chunk (32B sector)
#pragma unroll
        for (int j = 0; j < CC; j++) {
            int i  = tid + j * NTHR;
            int pp = i >> 3;      // pixel within tile
            int c  = i & 7;       // channel within chunk
            out[obase + pp * CTOT + c0 + c] = sStage[pp][c];
        }
    }
}

extern "C" void kernel_launch(void* const* d_in, const int* in_sizes, int n_in,
                              void* d_out, int out_size)
{
    const float* q = (const float*)d_in[0];
    const float* k = (const float*)d_in[1];
    const float* v = (const float*)d_in[2];
    float* out = (float*)d_out;

    dim3 grid(HT / TY, HEADS, BD);   // 7 x 12 x 8 = 672 blocks
    dilate_attn_kernel<<<grid, NTHR>>>(q, k, v, out);
}